// round 16
// baseline (speedup 1.0000x reference)
#include <cuda_runtime.h>
#include <cuda_fp16.h>
#include <cstdint>
#include <math.h>

#define N_SENTC 256
#define BATCH   512
#define SEQ     128
#define DIM     1024
#define LBL     10331
#define LATD    101
#define LATP    128
#define DIM2    2048
#define NEGV    (-10000.0f)

// ---------------- scratch -----------------------------------------------------
__device__ __half g_C1h[(size_t)N_SENTC * SEQ * DIM];   // fp16 C1
__device__ float g_menScore[N_SENTC * SEQ];
__device__ float g_m2[BATCH * DIM];
__device__ float g_lat32[BATCH * LATP];

// fp16 operand scratch
__device__ __half g_eF[(size_t)N_SENTC * SEQ * DIM];
__device__ __half g_WmF[DIM * DIM];
__device__ __half g_WcF[DIM * DIM];
__device__ __half g_WcmF[DIM * DIM];
__device__ __half g_WoF[(size_t)LBL * DIM2];
__device__ __half g_Wl2lF[(size_t)LBL * LATP];
__device__ __half g_Wf2lF[(size_t)LATD * DIM2];
__device__ __half g_fF[BATCH * DIM2];
__device__ __half g_latF[BATCH * LATP];

// ---------------- helpers -----------------------------------------------------
__device__ __forceinline__ uint32_t smem_to_u32(const void* p) {
    uint32_t a;
    asm("{ .reg .u64 t; cvta.to.shared.u64 t, %1; cvt.u32.u64 %0, t; }" : "=r"(a) : "l"(p));
    return a;
}
__device__ __forceinline__ float ftanh(float x) {
    float e = __expf(2.0f * x);
    return 1.0f - __fdividef(2.0f, e + 1.0f);
}

// zero three float arrays in one launch
__global__ void zero3_kernel(float* p0, int n0, float* p1, int n1, float* p2, int n2) {
    int i = blockIdx.x * blockDim.x + threadIdx.x;
    if (i < n0) { p0[i] = 0.0f; return; }
    i -= n0;
    if (i < n1) { p1[i] = 0.0f; return; }
    i -= n1;
    if (i < n2) p2[i] = 0.0f;
}

__global__ void cvt_f16(const float* __restrict__ src, __half* __restrict__ dst, int n4) {
    int i = blockIdx.x * blockDim.x + threadIdx.x;
    if (i < n4) {
        float4 v = reinterpret_cast<const float4*>(src)[i];
        __half2 a = __floats2half2_rn(v.x, v.y);
        __half2 b = __floats2half2_rn(v.z, v.w);
        uint2 o;
        o.x = *reinterpret_cast<uint32_t*>(&a);
        o.y = *reinterpret_cast<uint32_t*>(&b);
        reinterpret_cast<uint2*>(dst)[i] = o;
    }
}

__global__ void cvt2_f16(const float* __restrict__ s1, __half* __restrict__ d1,
                         const float* __restrict__ s2, __half* __restrict__ d2, int n4) {
    int i = blockIdx.x * blockDim.x + threadIdx.x;
    const float* s = (i < n4) ? s1 : s2;
    __half* d      = (i < n4) ? d1 : d2;
    int j = (i < n4) ? i : i - n4;
    if (j < n4 && i < 2 * n4) {
        float4 v = reinterpret_cast<const float4*>(s)[j];
        __half2 a = __floats2half2_rn(v.x, v.y);
        __half2 b = __floats2half2_rn(v.z, v.w);
        uint2 o;
        o.x = *reinterpret_cast<uint32_t*>(&a);
        o.y = *reinterpret_cast<uint32_t*>(&b);
        reinterpret_cast<uint2*>(d)[j] = o;
    }
}

__global__ void cvt_l2l(const float* __restrict__ src, __half* __restrict__ dst) {
    int i = blockIdx.x * blockDim.x + threadIdx.x;
    if (i < LBL * LATP) {
        int r = i >> 7, c = i & 127;
        float v = (c < LATD) ? src[r * LATD + c] : 0.0f;
        dst[i] = __float2half_rn(v);
    }
}

// pack fp32 latent accumulator -> fp16
__global__ void cvt_lat(const float* __restrict__ src, __half* __restrict__ dst) {
    int i = blockIdx.x * blockDim.x + threadIdx.x;
    if (i < BATCH * LATP) dst[i] = __float2half_rn(src[i]);
}

// ---------------- warp-mma + cp.async primitives ------------------------------
__device__ __forceinline__ void ldsm4(uint32_t* r, uint32_t addr) {
    asm volatile("ldmatrix.sync.aligned.m8n8.x4.shared.b16 {%0,%1,%2,%3}, [%4];"
                 : "=r"(r[0]), "=r"(r[1]), "=r"(r[2]), "=r"(r[3]) : "r"(addr));
}
__device__ __forceinline__ void mma16816(float (&c)[4], const uint32_t* a, const uint32_t* b) {
    asm volatile("mma.sync.aligned.m16n8k16.row.col.f32.f16.f16.f32 "
                 "{%0,%1,%2,%3}, {%4,%5,%6,%7}, {%8,%9}, {%0,%1,%2,%3};"
                 : "+f"(c[0]), "+f"(c[1]), "+f"(c[2]), "+f"(c[3])
                 : "r"(a[0]), "r"(a[1]), "r"(a[2]), "r"(a[3]), "r"(b[0]), "r"(b[1]));
}
__device__ __forceinline__ void cp16(uint32_t saddr, const void* gaddr, int src_size) {
    asm volatile("cp.async.cg.shared.global [%0], [%1], 16, %2;"
                 :: "r"(saddr), "l"(gaddr), "r"(src_size) : "memory");
}
#define CP_COMMIT() asm volatile("cp.async.commit_group;" ::: "memory")
#define CP_WAIT2()  asm volatile("cp.async.wait_group 2;" ::: "memory")

#define A_OFF 0
#define B_OFF 16384
#define STAGE_BYTES 49152
#define STAGES 4
#define SMEM_GEMM (STAGES * STAGE_BYTES)

// ---------------- core A: CTA 128x256, 8 warps, warp 64x64 (R14-proven) -------
__device__ __forceinline__ void gemm_core(
    const __half* __restrict__ A_, int lda,
    const __half* __restrict__ B_, int ldb,
    int N, int K, int m0, int n0, char* smem, float (&acc)[4][8][4])
{
    const uint32_t sb = smem_to_u32(smem);
    const int tid  = threadIdx.x;
    const int lane = tid & 31;
    const int wid  = tid >> 5;
    const int wm0  = (wid >> 2) * 64;
    const int wn0  = (wid & 3) * 64;
    const int nk   = K >> 6;

#pragma unroll
    for (int i = 0; i < 4; i++)
#pragma unroll
        for (int j = 0; j < 8; j++)
#pragma unroll
            for (int q = 0; q < 4; q++) acc[i][j][q] = 0.0f;

    const int aRow = lane & 15, aSel = lane >> 4;
    const int bRow = (lane & 7) + ((lane >> 4) << 3);
    const int bSel = (lane >> 3) & 1;
    const int crow = tid >> 3;
    const int cch  = tid & 7;
    const bool fullN = (n0 + 256 <= N);

    auto issue = [&](int c) {
        if (c >= nk) return;
        const int kb = c * 64;
        uint32_t stb = sb + (c & (STAGES - 1)) * STAGE_BYTES;
#pragma unroll
        for (int q = 0; q < 4; q++) {
            int row = crow + q * 32;
            uint32_t so = (uint32_t)(row * 128 + (((cch ^ (row & 7)) & 7) << 4));
            size_t ga = (size_t)(m0 + row) * lda + kb + cch * 8;
            cp16(stb + A_OFF + so, A_ + ga, 16);
        }
        if (fullN) {
#pragma unroll
            for (int q = 0; q < 8; q++) {
                int row = crow + q * 32;
                uint32_t so = (uint32_t)(row * 128 + (((cch ^ (row & 7)) & 7) << 4));
                size_t gb = (size_t)(n0 + row) * ldb + kb + cch * 8;
                cp16(stb + B_OFF + so, B_ + gb, 16);
            }
        } else {
#pragma unroll
            for (int q = 0; q < 8; q++) {
                int row = crow + q * 32;
                uint32_t so = (uint32_t)(row * 128 + (((cch ^ (row & 7)) & 7) << 4));
                int br = n0 + row;
                int ok = (br < N) ? 16 : 0;
                size_t gb = (size_t)min(br, N - 1) * ldb + kb + cch * 8;
                cp16(stb + B_OFF + so, B_ + gb, ok);
            }
        }
    };

    issue(0); CP_COMMIT();
    issue(1); CP_COMMIT();
    issue(2); CP_COMMIT();

    uint32_t aF[2][4][4], bF[2][4][4];

    for (int c = 0; c < nk; c++) {
        CP_WAIT2();
        __syncthreads();
        issue(c + 3); CP_COMMIT();
        uint32_t stb = sb + (c & (STAGES - 1)) * STAGE_BYTES;

        {
#pragma unroll
            for (int mf = 0; mf < 4; mf++) {
                int r = wm0 + mf * 16 + aRow;
                int ch = aSel;
                uint32_t o = (uint32_t)(r * 128 + (((ch ^ (r & 7)) & 7) << 4));
                ldsm4(aF[0][mf], stb + A_OFF + o);
            }
#pragma unroll
            for (int gg = 0; gg < 4; gg++) {
                int r = wn0 + gg * 16 + bRow;
                int ch = bSel;
                uint32_t o = (uint32_t)(r * 128 + (((ch ^ (r & 7)) & 7) << 4));
                ldsm4(bF[0][gg], stb + B_OFF + o);
            }
        }
#pragma unroll
        for (int ks = 0; ks < 4; ks++) {
            const int cur = ks & 1, nxt = cur ^ 1;
            if (ks < 3) {
                const int kc = (ks + 1) * 2;
#pragma unroll
                for (int mf = 0; mf < 4; mf++) {
                    int r = wm0 + mf * 16 + aRow;
                    int ch = kc + aSel;
                    uint32_t o = (uint32_t)(r * 128 + (((ch ^ (r & 7)) & 7) << 4));
                    ldsm4(aF[nxt][mf], stb + A_OFF + o);
                }
#pragma unroll
                for (int gg = 0; gg < 4; gg++) {
                    int r = wn0 + gg * 16 + bRow;
                    int ch = kc + bSel;
                    uint32_t o = (uint32_t)(r * 128 + (((ch ^ (r & 7)) & 7) << 4));
                    ldsm4(bF[nxt][gg], stb + B_OFF + o);
                }
            }
#pragma unroll
            for (int mf = 0; mf < 4; mf++) {
#pragma unroll
                for (int gg = 0; gg < 4; gg++) {
                    mma16816(acc[mf][gg * 2 + 0], aF[cur][mf], &bF[cur][gg][0]);
                    mma16816(acc[mf][gg * 2 + 1], aF[cur][mf], &bF[cur][gg][2]);
                }
            }
        }
    }
}

// ---------------- core B: CTA 128x128, warp 64x32 ------------------------------
#define A128_OFF 0
#define B128_OFF 16384
#define STAGE128_BYTES 32768
#define SMEM_GEMM128 (STAGES * STAGE128_BYTES)

__device__ __forceinline__ void gemm_core128(
    const __half* __restrict__ A_, int lda,
    const __half* __restrict__ B_, int ldb,
    int N, int K, int m0, int n0, char* smem, float (&acc)[4][4][4])
{
    const uint32_t sb = smem_to_u32(smem);
    const int tid  = threadIdx.x;
    const int lane = tid & 31;
    const int wid  = tid >> 5;
    const int wm0  = (wid >> 2) * 64;
    const int wn0  = (wid & 3) * 32;
    const int nk   = K >> 6;

#pragma unroll
    for (int i = 0; i < 4; i++)
#pragma unroll
        for (int j = 0; j < 4; j++)
#pragma unroll
            for (int q = 0; q < 4; q++) acc[i][j][q] = 0.0f;

    const int aRow = lane & 15, aSel = lane >> 4;
    const int bRow = (lane & 7) + ((lane >> 4) << 3);
    const int bSel = (lane >> 3) & 1;
    const int crow = tid >> 3;
    const int cch  = tid & 7;

    auto issue = [&](int c) {
        if (c >= nk) return;
        const int kb = c * 64;
        uint32_t stb = sb + (c & (STAGES - 1)) * STAGE128_BYTES;
#pragma unroll
        for (int q = 0; q < 4; q++) {
            int row = crow + q * 32;
            uint32_t so = (uint32_t)(row * 128 + (((cch ^ (row & 7)) & 7) << 4));
            size_t ga = (size_t)(m0 + row) * lda + kb + cch * 8;
            cp16(stb + A128_OFF + so, A_ + ga, 16);
        }
#pragma unroll
        for (int q = 0; q < 4; q++) {
            int row = crow + q * 32;
            uint32_t so = (uint32_t)(row * 128 + (((cch ^ (row & 7)) & 7) << 4));
            int br = n0 + row;
            int ok = (br < N) ? 16 : 0;
            size_t gb = (size_t)min(br, N - 1) * ldb + kb + cch * 8;
            cp16(stb + B128_OFF + so, B_ + gb, ok);
        }
    };

    issue(0); CP_COMMIT();
    issue(1); CP_COMMIT();
    issue(2); CP_COMMIT();

    uint32_t aF[2][4][4], bF[2][2][4];

    for (int c = 0; c < nk; c++) {
        CP_WAIT2();
        __syncthreads();
        issue(c + 3); CP_COMMIT();
        uint32_t stb = sb + (c & (STAGES - 1)) * STAGE128_BYTES;

        {
#pragma unroll
            for (int mf = 0; mf < 4; mf++) {
                int r = wm0 + mf * 16 + aRow;
                int ch = aSel;
                uint32_t o = (uint32_t)(r * 128 + (((ch ^ (r & 7)) & 7) << 4));
                ldsm4(aF[0][mf], stb + A128_OFF + o);
            }
#pragma unroll
            for (int p = 0; p < 2; p++) {
                int r = wn0 + p * 16 + bRow;
                int ch = bSel;
                uint32_t o = (uint32_t)(r * 128 + (((ch ^ (r & 7)) & 7) << 4));
                ldsm4(bF[0][p], stb + B128_OFF + o);
            }
        }
#pragma unroll
        for (int ks = 0; ks < 4; ks++) {
            const int cur = ks & 1, nxt = cur ^ 1;
            if (ks < 3) {
                const int kc = (ks + 1) * 2;
#pragma unroll
                for (int mf = 0; mf < 4; mf++) {
                    int r = wm0 + mf * 16 + aRow;
                    int ch = kc + aSel;
                    uint32_t o = (uint32_t)(r * 128 + (((ch ^ (r & 7)) & 7) << 4));
                    ldsm4(aF[nxt][mf], stb + A128_OFF + o);
                }
#pragma unroll
                for (int p = 0; p < 2; p++) {
                    int r = wn0 + p * 16 + bRow;
                    int ch = kc + bSel;
                    uint32_t o = (uint32_t)(r * 128 + (((ch ^ (r & 7)) & 7) << 4));
                    ldsm4(bF[nxt][p], stb + B128_OFF + o);
                }
            }
#pragma unroll
            for (int mf = 0; mf < 4; mf++) {
#pragma unroll
                for (int nf = 0; nf < 4; nf++) {
                    mma16816(acc[mf][nf], aF[cur][mf], &bF[cur][nf >> 1][(nf & 1) * 2]);
                }
            }
        }
    }
}

// ---------------- fused big kernel: mention scores + C1 (fp16) ----------------
__global__ __launch_bounds__(256, 1)
void gemm_big(const __half* __restrict__ eF,
              const __half* __restrict__ wmF, const __half* __restrict__ wcF,
              const float* __restrict__ wo, float* __restrict__ rowAcc,
              __half* __restrict__ C1)
{
    extern __shared__ char smem[];
    const bool isMen = blockIdx.x < 4;
    const int n0 = (blockIdx.x & 3) * 256;
    const int m0 = blockIdx.y * 128;
    const int lane = threadIdx.x & 31;
    const int wid  = threadIdx.x >> 5;
    const int wm0  = (wid >> 2) * 64;
    const int wn0  = (wid & 3) * 64;

    float acc[4][8][4];
    gemm_core(eF, DIM, isMen ? wmF : wcF, DIM, DIM, DIM, m0, n0, smem, acc);

    const int g = lane >> 2, t = lane & 3;
    if (isMen) {
#pragma unroll
        for (int mf = 0; mf < 4; mf++) {
            float s0 = 0.0f, s1 = 0.0f;
#pragma unroll
            for (int nf = 0; nf < 8; nf++) {
#pragma unroll
                for (int q = 0; q < 2; q++) {
                    int n = n0 + wn0 + nf * 8 + 2 * t + q;
                    float w = wo[n];
                    s0 += ftanh(acc[mf][nf][q])     * w;
                    s1 += ftanh(acc[mf][nf][2 + q]) * w;
                }
            }
            s0 += __shfl_xor_sync(0xffffffffu, s0, 1);
            s0 += __shfl_xor_sync(0xffffffffu, s0, 2);
            s1 += __shfl_xor_sync(0xffffffffu, s1, 1);
            s1 += __shfl_xor_sync(0xffffffffu, s1, 2);
            if (t == 0) {
                int m = m0 + wm0 + mf * 16 + g;
                atomicAdd(&rowAcc[m], s0);
                atomicAdd(&rowAcc[m + 8], s1);
            }
        }
    } else {
#pragma unroll
        for (int mf = 0; mf < 4; mf++) {
            int mA = m0 + wm0 + mf * 16 + g;
#pragma unroll
            for (int nf = 0; nf < 8; nf++) {
                int n = n0 + wn0 + nf * 8 + 2 * t;
                size_t iA = (size_t)mA * DIM + n;
                size_t iB = (size_t)(mA + 8) * DIM + n;
                *reinterpret_cast<__half2*>(C1 + iA) =
                    __floats2half2_rn(acc[mf][nf][0], acc[mf][nf][1]);
                *reinterpret_cast<__half2*>(C1 + iB) =
                    __floats2half2_rn(acc[mf][nf][2], acc[mf][nf][3]);
            }
        }
    }
}

// ---------------- split-K GEMM, 256-wide tile, atomicAdd epilogue (m2) ---------
__global__ __launch_bounds__(256, 1)
void gemm_ks256(const __half* __restrict__ A_, int lda,
                const __half* __restrict__ B_, int ldb,
                float* __restrict__ C, int ldc, int N, int Kslice)
{
    extern __shared__ char smem[];
    const int n0 = blockIdx.x * 256;
    const int m0 = blockIdx.y * 128;
    const int kofs = blockIdx.z * Kslice;
    const int lane = threadIdx.x & 31;
    const int wid  = threadIdx.x >> 5;
    const int wm0  = (wid >> 2) * 64;
    const int wn0  = (wid & 3) * 64;

    float acc[4][8][4];
    gemm_core(A_ + kofs, lda, B_ + kofs, ldb, N, Kslice, m0, n0, smem, acc);

    const int g = lane >> 2, t = lane & 3;
#pragma unroll
    for (int mf = 0; mf < 4; mf++) {
        int mA = m0 + wm0 + mf * 16 + g;
#pragma unroll
        for (int nf = 0; nf < 8; nf++) {
            int n = n0 + wn0 + nf * 8 + 2 * t;
#pragma unroll
            for (int q = 0; q < 2; q++) {
                int nn = n + q;
                if (nn < N) {
                    atomicAdd(&C[(size_t)mA * ldc + nn],       acc[mf][nf][q]);
                    atomicAdd(&C[(size_t)(mA + 8) * ldc + nn], acc[mf][nf][2 + q]);
                }
            }
        }
    }
}

// ---------------- split-K GEMM, 128-wide tile, atomicAdd (latent) --------------
__global__ __launch_bounds__(256, 1)
void gemm_ks128(const __half* __restrict__ A_, int lda,
                const __half* __restrict__ B_, int ldb,
                float* __restrict__ C, int ldc, int N, int Kslice)
{
    extern __shared__ char smem[];
    const int n0 = blockIdx.x * 128;
    const int m0 = blockIdx.y * 128;
    const int kofs = blockIdx.z * Kslice;
    const int lane = threadIdx.x & 31;
    const int wid  = threadIdx.x >> 5;
    const int wm0  = (wid >> 2) * 64;
    const int wn0  = (wid & 3) * 32;

    float acc[4][4][4];
    gemm_core128(A_ + kofs, lda, B_ + kofs, ldb, N, Kslice, m0, n0, smem, acc);

    const int g = lane >> 2, t = lane & 3;
#pragma unroll
    for (int mf = 0; mf < 4; mf++) {
        int mA = m0 + wm0 + mf * 16 + g;
#pragma unroll
        for (int nf = 0; nf < 4; nf++) {
            int n = n0 + wn0 + nf * 8 + 2 * t;
#pragma unroll
            for (int q = 0; q < 2; q++) {
                int nn = n + q;
                if (nn < N) {
                    atomicAdd(&C[(size_t)mA * ldc + nn],       acc[mf][nf][q]);
                    atomicAdd(&C[(size_t)(mA + 8) * ldc + nn], acc[mf][nf][2 + q]);
                }
            }
        }
    }
}

// ---------------- fused output head: out_lat + out_main (tile 128x128) --------
__global__ __launch_bounds__(256, 1)
void gemm_outfused(const __half* __restrict__ latF,
                   const __half* __restrict__ l2lF,
                   const __half* __restrict__ fF,
                   const __half* __restrict__ woF,
                   float* __restrict__ outLat,
                   float* __restrict__ outMain,
                   const float* __restrict__ scal)
{
    extern __shared__ char smem[];
    const int n0 = blockIdx.x * 128;
    const int m0 = blockIdx.y * 128;
    const int lane = threadIdx.x & 31;
    const int wid  = threadIdx.x >> 5;
    const int wm0  = (wid >> 2) * 64;
    const int wn0  = (wid & 3) * 32;

    float accL[4][4][4];
    gemm_core128(latF, LATP, l2lF, LATP, LBL, LATP, m0, n0, smem, accL);
    __syncthreads();

    float acc[4][4][4];
    gemm_core128(fF, DIM2, woF, DIM2, LBL, DIM2, m0, n0, smem, acc);

    const int g = lane >> 2, t = lane & 3;
    const float ls = *scal;
#pragma unroll
    for (int mf = 0; mf < 4; mf++) {
        int mA = m0 + wm0 + mf * 16 + g;
#pragma unroll
        for (int nf = 0; nf < 4; nf++) {
            int n = n0 + wn0 + nf * 8 + 2 * t;
#pragma unroll
            for (int q = 0; q < 2; q++) {
                int nn = n + q;
                if (nn < LBL) {
                    size_t iA = (size_t)mA * LBL + nn;
                    size_t iB = (size_t)(mA + 8) * LBL + nn;
                    float l0 = accL[mf][nf][q];
                    float l1 = accL[mf][nf][2 + q];
                    outLat[iA]  = l0;
                    outLat[iB]  = l1;
                    outMain[iA] = acc[mf][nf][q]     + ls * l0;
                    outMain[iB] = acc[mf][nf][2 + q] + ls * l1;
                }
            }
        }
    }
}

// ---------------- mention: masked softmax + weighted sum (fp16) ---------------
__global__ void attn_kernel(const __half* __restrict__ elmoF,
                            const int* __restrict__ gathers,
                            const float* __restrict__ scores,
                            const float* __restrict__ mask,
                            __half* __restrict__ outF)
{
    int b = blockIdx.x;
    int tid = threadIdx.x;
    __shared__ float attn_s[SEQ];
    __shared__ float red[8];
    int g = gathers[b];

    float sc = -1e30f;
    if (tid < SEQ) {
        float raw = scores[g * SEQ + tid];
        sc = raw + (1.0f - mask[b * SEQ + tid]) * NEGV;
    }
    float v = sc;
#pragma unroll
    for (int off = 16; off > 0; off >>= 1)
        v = fmaxf(v, __shfl_xor_sync(0xffffffffu, v, off));
    if ((tid & 31) == 0) red[tid >> 5] = v;
    __syncthreads();
    float mx = fmaxf(fmaxf(red[0], red[1]), fmaxf(red[2], red[3]));
    __syncthreads();

    float e = (tid < SEQ) ? __expf(sc - mx) : 0.0f;
    v = e;
#pragma unroll
    for (int off = 16; off > 0; off >>= 1)
        v += __shfl_xor_sync(0xffffffffu, v, off);
    if ((tid & 31) == 0) red[tid >> 5] = v;
    __syncthreads();
    float sum = red[0] + red[1] + red[2] + red[3];
    if (tid < SEQ) attn_s[tid] = e / sum;
    __syncthreads();

    const uint2* xr = reinterpret_cast<const uint2*>(elmoF + (size_t)g * SEQ * DIM);
    float4 accv = make_float4(0.f, 0.f, 0.f, 0.f);
#pragma unroll 4
    for (int s = 0; s < SEQ; s++) {
        float a = attn_s[s];
        uint2 xp = xr[(size_t)s * (DIM / 4) + tid];
        float2 x0 = __half22float2(*reinterpret_cast<__half2*>(&xp.x));
        float2 x1 = __half22float2(*reinterpret_cast<__half2*>(&xp.y));
        accv.x = fmaf(a, x0.x, accv.x);
        accv.y = fmaf(a, x0.y, accv.y);
        accv.z = fmaf(a, x1.x, accv.z);
        accv.w = fmaf(a, x1.y, accv.w);
    }
    size_t idx = (size_t)b * DIM2 + 4 * tid;
    __half2 h0 = __floats2half2_rn(accv.x, accv.y);
    __half2 h1 = __floats2half2_rn(accv.z, accv.w);
    uint2 o;
    o.x = *reinterpret_cast<uint32_t*>(&h0);
    o.y = *reinterpret_cast<uint32_t*>(&h1);
    *reinterpret_cast<uint2*>(outF + idx) = o;
}

// ---------------- fused context: score + softmax + weighted sum ----------------
__global__ void ctx_fused_kernel(const int* __restrict__ gathers,
                                 const float* __restrict__ dist,
                                 const float* __restrict__ wd,
                                 const float* __restrict__ wo,
                                 const float* __restrict__ mask,
                                 const __half* __restrict__ elmoF,
                                 __half* __restrict__ outF)
{
    int b = blockIdx.x;
    int tid = threadIdx.x;
    int w = tid >> 5, lid = tid & 31;
    __shared__ __align__(16) float s_m2[DIM];
    __shared__ __align__(16) float s_wd[DIM];
    __shared__ __align__(16) float s_wo[DIM];
    __shared__ float s_score[SEQ];
    __shared__ float attn_s[SEQ];
    __shared__ float red[8];
    int g = gathers[b];
    for (int i = tid; i < DIM; i += 256) {
        s_m2[i] = g_m2[(size_t)b * DIM + i];
        s_wd[i] = wd[i];
        s_wo[i] = wo[i];
    }
    __syncthreads();

    const uint2* c1 = reinterpret_cast<const uint2*>(g_C1h + (size_t)g * SEQ * DIM);
    const float4* m2v = reinterpret_cast<const float4*>(s_m2);
    const float4* wdv = reinterpret_cast<const float4*>(s_wd);
    const float4* wov = reinterpret_cast<const float4*>(s_wo);

    for (int s = w; s < SEQ; s += 8) {
        float dv = dist[b * SEQ + s];
        float p = 0.0f;
#pragma unroll
        for (int j0 = 0; j0 < 8; j0++) {
            int j = lid + j0 * 32;
            uint2 cp = c1[(size_t)s * (DIM / 4) + j];
            float2 c0 = __half22float2(*reinterpret_cast<__half2*>(&cp.x));
            float2 c1f = __half22float2(*reinterpret_cast<__half2*>(&cp.y));
            float4 m = m2v[j], d = wdv[j], o = wov[j];
            p += o.x * ftanh(c0.x  + m.x + dv * d.x)
               + o.y * ftanh(c0.y  + m.y + dv * d.y)
               + o.z * ftanh(c1f.x + m.z + dv * d.z)
               + o.w * ftanh(c1f.y + m.w + dv * d.w);
        }
#pragma unroll
        for (int off = 16; off > 0; off >>= 1)
            p += __shfl_xor_sync(0xffffffffu, p, off);
        if (lid == 0) s_score[s] = p;
    }
    __syncthreads();

    float sc = -1e30f;
    if (tid < SEQ)
        sc = s_score[tid] + (1.0f - mask[b * SEQ + tid]) * NEGV;
    float v = sc;
#pragma unroll
    for (int off = 16; off > 0; off >>= 1)
        v = fmaxf(v, __shfl_xor_sync(0xffffffffu, v, off));
    if ((tid & 31) == 0) red[tid >> 5] = v;
    __syncthreads();
    float mx = fmaxf(fmaxf(red[0], red[1]), fmaxf(red[2], red[3]));
    __syncthreads();
    float e = (tid < SEQ) ? __expf(sc - mx) : 0.0f;
    v = e;
#pragma unroll
    for (int off = 16; off > 0; off >>= 1)
        v += __shfl_xor_sync(0xffffffffu, v, off);
    if ((tid & 31) == 0) red[tid >> 5] = v;
    __syncthreads();
    float sum = red[0] + red[1] + red[2] + red[3];
    if (tid < SEQ) attn_s[tid] = e / sum;
    __syncthreads();

    const uint2* xr = reinterpret_cast<const uint2*>(elmoF + (size_t)g * SEQ * DIM);
    float4 accv = make_float4(0.f, 0.f, 0.f, 0.f);
#pragma unroll 4
    for (int s = 0; s < SEQ; s++) {
        float a = attn_s[s];
        uint2 xp = xr[(size_t)s * (DIM / 4) + tid];
        float2 x0 = __half22float2(*reinterpret_cast<__half2*>(&xp.x));
        float2 x1 = __half22float2(*reinterpret_cast<__half2*>(&xp.y));
        accv.x = fmaf(a, x0.x, accv.x);
        accv.y = fmaf(a, x0.y, accv.y);
        accv.z = fmaf(a, x1.x, accv.z);
        accv.w = fmaf(a, x1.y, accv.w);
    }
    size_t idx = (size_t)b * DIM2 + DIM + 4 * tid;
    __half2 h0 = __floats2half2_rn(accv.x, accv.y);
    __half2 h1 = __floats2half2_rn(accv.z, accv.w);
    uint2 o;
    o.x = *reinterpret_cast<uint32_t*>(&h0);
    o.y = *reinterpret_cast<uint32_t*>(&h1);
    *reinterpret_cast<uint2*>(outF + idx) = o;
}

// ---------------- launch ------------------------------------------------------
extern "C" void kernel_launch(void* const* d_in, const int* in_sizes, int n_in,
                              void* d_out, int out_size)
{
    const float* elmo     = (const float*)d_in[0];
    const float* men_mask = (const float*)d_in[1];
    const float* ctx_mask = (const float*)d_in[2];
    const float* dist     = (const float*)d_in[3];
    const int*   gathers  = (const int*)  d_in[4];
    const float* W_men_m  = (const float*)d_in[5];
    const float* W_men_o  = (const float*)d_in[6];
    const float* W_ctx_c  = (const float*)d_in[7];
    const float* W_ctx_m  = (const float*)d_in[8];
    const float* w_ctx_d  = (const float*)d_in[9];
    const float* W_ctx_o  = (const float*)d_in[10];
    const float* W_out    = (const float*)d_in[11];
    const float* W_f2l    = (const float*)d_in[12];
    const float* W_l2l    = (const float*)d_in[13];
    const float* lscal    = (const float*)d_in[14];

    float* out_main = (float*)d_out;
    float* out_lat  = out_main + (size_t)BATCH * LBL;

    float *pMS, *pM2, *pLat32;
    __half* pC1;
    cudaGetSymbolAddress((void**)&pC1,    g_C1h);
    cudaGetSymbolAddress((void**)&pMS,    g_menScore);
    cudaGetSymbolAddress((void**)&pM2,    g_m2);
    cudaGetSymbolAddress((void**)&pLat32, g_lat32);
    __half *pEF, *pWmF, *pWcF, *pWcmF, *pWoF, *pl2lF, *pf2lF, *pFF, *pLaF;
    cudaGetSymbolAddress((void**)&pEF,   g_eF);
    cudaGetSymbolAddress((void**)&pWmF,  g_WmF);
    cudaGetSymbolAddress((void**)&pWcF,  g_WcF);
    cudaGetSymbolAddress((void**)&pWcmF, g_WcmF);
    cudaGetSymbolAddress((void**)&pWoF,  g_WoF);
    cudaGetSymbolAddress((void**)&pl2lF, g_Wl2lF);
    cudaGetSymbolAddress((void**)&pf2lF, g_Wf2lF);
    cudaGetSymbolAddress((void**)&pFF,   g_fF);
    cudaGetSymbolAddress((void**)&pLaF,  g_latF);

    cudaFuncSetAttribute(gemm_big,      cudaFuncAttributeMaxDynamicSharedMemorySize, SMEM_GEMM);
    cudaFuncSetAttribute(gemm_ks256,    cudaFuncAttributeMaxDynamicSharedMemorySize, SMEM_GEMM);
    cudaFuncSetAttribute(gemm_ks128,    cudaFuncAttributeMaxDynamicSharedMemorySize, SMEM_GEMM128);
    cudaFuncSetAttribute(gemm_outfused, cudaFuncAttributeMaxDynamicSharedMemorySize, SMEM_GEMM128);

    const int nDD4 = (DIM * DIM) / 4;

    // 0. elmo fp32->fp16
    {
        int n4 = (N_SENTC * SEQ * DIM) / 4;
        cvt_f16<<<(n4 + 255) / 256, 256>>>(elmo, pEF, n4);
    }
    // 1. W_men_m + W_ctx_c in one launch
    cvt2_f16<<<(2 * nDD4 + 255) / 256, 256>>>(W_men_m, pWmF, W_ctx_c, pWcF, nDD4);
    // 2. zero menScore + m2 + lat32
    {
        int ntot = N_SENTC * SEQ + BATCH * DIM + BATCH * LATP;
        zero3_kernel<<<(ntot + 255) / 256, 256>>>(pMS, N_SENTC * SEQ,
                                                  pM2, BATCH * DIM,
                                                  pLat32, BATCH * LATP);
    }

    // 3. fused big GEMM (ncu window: launch index 3)
    gemm_big<<<dim3(8, 256), 256, SMEM_GEMM>>>(pEF, pWmF, pWcF, W_men_o, pMS, pC1);

    // 4-7. remaining conversions
    cvt_f16<<<(nDD4 + 255) / 256, 256>>>(W_ctx_m, pWcmF, nDD4);
    {
        int n4o = (int)(((size_t)LBL * DIM2) / 4);
        cvt_f16<<<(n4o + 255) / 256, 256>>>(W_out, pWoF, n4o);
    }
    cvt_l2l<<<(LBL * LATP + 255) / 256, 256>>>(W_l2l, pl2lF);
    {
        int n4f = (LATD * DIM2) / 4;
        cvt_f16<<<(n4f + 255) / 256, 256>>>(W_f2l, pf2lF, n4f);
    }

    // 8. mention softmax + men_repr -> fF cols [0,1024)
    attn_kernel<<<BATCH, 256>>>(pEF, gathers, pMS, men_mask, pFF);

    // 9. m2 = men_repr @ W_ctx_m^T, split-K 4x256 -> atomicAdd (64 CTAs)
    gemm_ks256<<<dim3(4, 4, 4), 256, SMEM_GEMM>>>(
        pFF, DIM2, pWcmF, DIM, pM2, DIM, DIM, 256);

    // 10. fused context: score + softmax + ctx_repr -> fF cols [1024,2048)
    ctx_fused_kernel<<<BATCH, 256>>>(gathers, dist, w_ctx_d, W_ctx_o,
                                     ctx_mask, pEF, pFF);

    // 11. latent = final @ W_f2l^T, split-K 8x256 -> atomicAdd (32 CTAs)
    gemm_ks128<<<dim3(1, 4, 8), 256, SMEM_GEMM128>>>(
        pFF, DIM2, pf2lF, DIM2, pLat32, LATP, LATD, 256);

    // 12. pack latent fp32 -> fp16
    cvt_lat<<<(BATCH * LATP + 255) / 256, 256>>>(pLat32, pLaF);

    // 13. fused output head: out_lat + out_main in one pass (tile 128x128)
    gemm_outfused<<<dim3((LBL + 127) / 128, 4), 256, SMEM_GEMM128>>>(
        pLaF, pl2lF, pFF, pWoF, out_lat, out_main, lscal);
}

// round 17
// speedup vs baseline: 1.4270x; 1.4270x over previous
#include <cuda_runtime.h>
#include <cuda_fp16.h>
#include <cstdint>
#include <math.h>

#define N_SENTC 256
#define BATCH   512
#define SEQ     128
#define DIM     1024
#define LBL     10331
#define LATD    101
#define LATP    128
#define DIM2    2048
#define NEGV    (-10000.0f)

// ---------------- scratch -----------------------------------------------------
__device__ __half g_C1h[(size_t)N_SENTC * SEQ * DIM];   // fp16 C1
__device__ float g_menScore[N_SENTC * SEQ];
__device__ float g_m2[BATCH * DIM];
__device__ float g_lat32[BATCH * LATP];

// fp16 operand scratch
__device__ __half g_eF[(size_t)N_SENTC * SEQ * DIM];
__device__ __half g_WmF[DIM * DIM];
__device__ __half g_WcF[DIM * DIM];
__device__ __half g_WcmF[DIM * DIM];
__device__ __half g_WoF[(size_t)LBL * DIM2];
__device__ __half g_Wl2lF[(size_t)LBL * LATP];
__device__ __half g_Wf2lF[(size_t)LATD * DIM2];
__device__ __half g_fF[BATCH * DIM2];
__device__ __half g_latF[BATCH * LATP];

// ---------------- helpers -----------------------------------------------------
__device__ __forceinline__ uint32_t smem_to_u32(const void* p) {
    uint32_t a;
    asm("{ .reg .u64 t; cvta.to.shared.u64 t, %1; cvt.u32.u64 %0, t; }" : "=r"(a) : "l"(p));
    return a;
}
__device__ __forceinline__ float ftanh(float x) {
    float e = __expf(2.0f * x);
    return 1.0f - __fdividef(2.0f, e + 1.0f);
}

// zero two float arrays in one launch
__global__ void zero2_kernel(float* p0, int n0, float* p1, int n1) {
    int i = blockIdx.x * blockDim.x + threadIdx.x;
    if (i < n0) { p0[i] = 0.0f; return; }
    i -= n0;
    if (i < n1) p1[i] = 0.0f;
}

__global__ void cvt_f16(const float* __restrict__ src, __half* __restrict__ dst, int n4) {
    int i = blockIdx.x * blockDim.x + threadIdx.x;
    if (i < n4) {
        float4 v = reinterpret_cast<const float4*>(src)[i];
        __half2 a = __floats2half2_rn(v.x, v.y);
        __half2 b = __floats2half2_rn(v.z, v.w);
        uint2 o;
        o.x = *reinterpret_cast<uint32_t*>(&a);
        o.y = *reinterpret_cast<uint32_t*>(&b);
        reinterpret_cast<uint2*>(dst)[i] = o;
    }
}

__global__ void cvt2_f16(const float* __restrict__ s1, __half* __restrict__ d1,
                         const float* __restrict__ s2, __half* __restrict__ d2, int n4) {
    int i = blockIdx.x * blockDim.x + threadIdx.x;
    const float* s = (i < n4) ? s1 : s2;
    __half* d      = (i < n4) ? d1 : d2;
    int j = (i < n4) ? i : i - n4;
    if (j < n4 && i < 2 * n4) {
        float4 v = reinterpret_cast<const float4*>(s)[j];
        __half2 a = __floats2half2_rn(v.x, v.y);
        __half2 b = __floats2half2_rn(v.z, v.w);
        uint2 o;
        o.x = *reinterpret_cast<uint32_t*>(&a);
        o.y = *reinterpret_cast<uint32_t*>(&b);
        reinterpret_cast<uint2*>(d)[j] = o;
    }
}

__global__ void cvt_l2l(const float* __restrict__ src, __half* __restrict__ dst) {
    int i = blockIdx.x * blockDim.x + threadIdx.x;
    if (i < LBL * LATP) {
        int r = i >> 7, c = i & 127;
        float v = (c < LATD) ? src[r * LATD + c] : 0.0f;
        dst[i] = __float2half_rn(v);
    }
}

// pack fp32 latent accumulator -> fp16
__global__ void cvt_lat(const float* __restrict__ src, __half* __restrict__ dst) {
    int i = blockIdx.x * blockDim.x + threadIdx.x;
    if (i < BATCH * LATP) dst[i] = __float2half_rn(src[i]);
}

// ---------------- warp-mma + cp.async primitives ------------------------------
__device__ __forceinline__ void ldsm4(uint32_t* r, uint32_t addr) {
    asm volatile("ldmatrix.sync.aligned.m8n8.x4.shared.b16 {%0,%1,%2,%3}, [%4];"
                 : "=r"(r[0]), "=r"(r[1]), "=r"(r[2]), "=r"(r[3]) : "r"(addr));
}
__device__ __forceinline__ void mma16816(float (&c)[4], const uint32_t* a, const uint32_t* b) {
    asm volatile("mma.sync.aligned.m16n8k16.row.col.f32.f16.f16.f32 "
                 "{%0,%1,%2,%3}, {%4,%5,%6,%7}, {%8,%9}, {%0,%1,%2,%3};"
                 : "+f"(c[0]), "+f"(c[1]), "+f"(c[2]), "+f"(c[3])
                 : "r"(a[0]), "r"(a[1]), "r"(a[2]), "r"(a[3]), "r"(b[0]), "r"(b[1]));
}
__device__ __forceinline__ void cp16(uint32_t saddr, const void* gaddr, int src_size) {
    asm volatile("cp.async.cg.shared.global [%0], [%1], 16, %2;"
                 :: "r"(saddr), "l"(gaddr), "r"(src_size) : "memory");
}
#define CP_COMMIT() asm volatile("cp.async.commit_group;" ::: "memory")
#define CP_WAIT2()  asm volatile("cp.async.wait_group 2;" ::: "memory")

#define A_OFF 0
#define B_OFF 16384
#define STAGE_BYTES 49152
#define STAGES 4
#define SMEM_GEMM (STAGES * STAGE_BYTES)

// ---------------- core A: CTA 128x256, 8 warps, warp 64x64 (R14-proven) -------
__device__ __forceinline__ void gemm_core(
    const __half* __restrict__ A_, int lda,
    const __half* __restrict__ B_, int ldb,
    int N, int K, int m0, int n0, char* smem, float (&acc)[4][8][4])
{
    const uint32_t sb = smem_to_u32(smem);
    const int tid  = threadIdx.x;
    const int lane = tid & 31;
    const int wid  = tid >> 5;
    const int wm0  = (wid >> 2) * 64;
    const int wn0  = (wid & 3) * 64;
    const int nk   = K >> 6;

#pragma unroll
    for (int i = 0; i < 4; i++)
#pragma unroll
        for (int j = 0; j < 8; j++)
#pragma unroll
            for (int q = 0; q < 4; q++) acc[i][j][q] = 0.0f;

    const int aRow = lane & 15, aSel = lane >> 4;
    const int bRow = (lane & 7) + ((lane >> 4) << 3);
    const int bSel = (lane >> 3) & 1;
    const int crow = tid >> 3;
    const int cch  = tid & 7;
    const bool fullN = (n0 + 256 <= N);

    auto issue = [&](int c) {
        if (c >= nk) return;
        const int kb = c * 64;
        uint32_t stb = sb + (c & (STAGES - 1)) * STAGE_BYTES;
#pragma unroll
        for (int q = 0; q < 4; q++) {
            int row = crow + q * 32;
            uint32_t so = (uint32_t)(row * 128 + (((cch ^ (row & 7)) & 7) << 4));
            size_t ga = (size_t)(m0 + row) * lda + kb + cch * 8;
            cp16(stb + A_OFF + so, A_ + ga, 16);
        }
        if (fullN) {
#pragma unroll
            for (int q = 0; q < 8; q++) {
                int row = crow + q * 32;
                uint32_t so = (uint32_t)(row * 128 + (((cch ^ (row & 7)) & 7) << 4));
                size_t gb = (size_t)(n0 + row) * ldb + kb + cch * 8;
                cp16(stb + B_OFF + so, B_ + gb, 16);
            }
        } else {
#pragma unroll
            for (int q = 0; q < 8; q++) {
                int row = crow + q * 32;
                uint32_t so = (uint32_t)(row * 128 + (((cch ^ (row & 7)) & 7) << 4));
                int br = n0 + row;
                int ok = (br < N) ? 16 : 0;
                size_t gb = (size_t)min(br, N - 1) * ldb + kb + cch * 8;
                cp16(stb + B_OFF + so, B_ + gb, ok);
            }
        }
    };

    issue(0); CP_COMMIT();
    issue(1); CP_COMMIT();
    issue(2); CP_COMMIT();

    uint32_t aF[2][4][4], bF[2][4][4];

    for (int c = 0; c < nk; c++) {
        CP_WAIT2();
        __syncthreads();
        issue(c + 3); CP_COMMIT();
        uint32_t stb = sb + (c & (STAGES - 1)) * STAGE_BYTES;

        {
#pragma unroll
            for (int mf = 0; mf < 4; mf++) {
                int r = wm0 + mf * 16 + aRow;
                int ch = aSel;
                uint32_t o = (uint32_t)(r * 128 + (((ch ^ (r & 7)) & 7) << 4));
                ldsm4(aF[0][mf], stb + A_OFF + o);
            }
#pragma unroll
            for (int gg = 0; gg < 4; gg++) {
                int r = wn0 + gg * 16 + bRow;
                int ch = bSel;
                uint32_t o = (uint32_t)(r * 128 + (((ch ^ (r & 7)) & 7) << 4));
                ldsm4(bF[0][gg], stb + B_OFF + o);
            }
        }
#pragma unroll
        for (int ks = 0; ks < 4; ks++) {
            const int cur = ks & 1, nxt = cur ^ 1;
            if (ks < 3) {
                const int kc = (ks + 1) * 2;
#pragma unroll
                for (int mf = 0; mf < 4; mf++) {
                    int r = wm0 + mf * 16 + aRow;
                    int ch = kc + aSel;
                    uint32_t o = (uint32_t)(r * 128 + (((ch ^ (r & 7)) & 7) << 4));
                    ldsm4(aF[nxt][mf], stb + A_OFF + o);
                }
#pragma unroll
                for (int gg = 0; gg < 4; gg++) {
                    int r = wn0 + gg * 16 + bRow;
                    int ch = kc + bSel;
                    uint32_t o = (uint32_t)(r * 128 + (((ch ^ (r & 7)) & 7) << 4));
                    ldsm4(bF[nxt][gg], stb + B_OFF + o);
                }
            }
#pragma unroll
            for (int mf = 0; mf < 4; mf++) {
#pragma unroll
                for (int gg = 0; gg < 4; gg++) {
                    mma16816(acc[mf][gg * 2 + 0], aF[cur][mf], &bF[cur][gg][0]);
                    mma16816(acc[mf][gg * 2 + 1], aF[cur][mf], &bF[cur][gg][2]);
                }
            }
        }
    }
}

// ---------------- core B: CTA 128x128, warp 64x32 ------------------------------
#define A128_OFF 0
#define B128_OFF 16384
#define STAGE128_BYTES 32768
#define SMEM_GEMM128 (STAGES * STAGE128_BYTES)

__device__ __forceinline__ void gemm_core128(
    const __half* __restrict__ A_, int lda,
    const __half* __restrict__ B_, int ldb,
    int N, int K, int m0, int n0, char* smem, float (&acc)[4][4][4])
{
    const uint32_t sb = smem_to_u32(smem);
    const int tid  = threadIdx.x;
    const int lane = tid & 31;
    const int wid  = tid >> 5;
    const int wm0  = (wid >> 2) * 64;
    const int wn0  = (wid & 3) * 32;
    const int nk   = K >> 6;

#pragma unroll
    for (int i = 0; i < 4; i++)
#pragma unroll
        for (int j = 0; j < 4; j++)
#pragma unroll
            for (int q = 0; q < 4; q++) acc[i][j][q] = 0.0f;

    const int aRow = lane & 15, aSel = lane >> 4;
    const int bRow = (lane & 7) + ((lane >> 4) << 3);
    const int bSel = (lane >> 3) & 1;
    const int crow = tid >> 3;
    const int cch  = tid & 7;

    auto issue = [&](int c) {
        if (c >= nk) return;
        const int kb = c * 64;
        uint32_t stb = sb + (c & (STAGES - 1)) * STAGE128_BYTES;
#pragma unroll
        for (int q = 0; q < 4; q++) {
            int row = crow + q * 32;
            uint32_t so = (uint32_t)(row * 128 + (((cch ^ (row & 7)) & 7) << 4));
            size_t ga = (size_t)(m0 + row) * lda + kb + cch * 8;
            cp16(stb + A128_OFF + so, A_ + ga, 16);
        }
#pragma unroll
        for (int q = 0; q < 4; q++) {
            int row = crow + q * 32;
            uint32_t so = (uint32_t)(row * 128 + (((cch ^ (row & 7)) & 7) << 4));
            int br = n0 + row;
            int ok = (br < N) ? 16 : 0;
            size_t gb = (size_t)min(br, N - 1) * ldb + kb + cch * 8;
            cp16(stb + B128_OFF + so, B_ + gb, ok);
        }
    };

    issue(0); CP_COMMIT();
    issue(1); CP_COMMIT();
    issue(2); CP_COMMIT();

    uint32_t aF[2][4][4], bF[2][2][4];

    for (int c = 0; c < nk; c++) {
        CP_WAIT2();
        __syncthreads();
        issue(c + 3); CP_COMMIT();
        uint32_t stb = sb + (c & (STAGES - 1)) * STAGE128_BYTES;

        {
#pragma unroll
            for (int mf = 0; mf < 4; mf++) {
                int r = wm0 + mf * 16 + aRow;
                int ch = aSel;
                uint32_t o = (uint32_t)(r * 128 + (((ch ^ (r & 7)) & 7) << 4));
                ldsm4(aF[0][mf], stb + A128_OFF + o);
            }
#pragma unroll
            for (int p = 0; p < 2; p++) {
                int r = wn0 + p * 16 + bRow;
                int ch = bSel;
                uint32_t o = (uint32_t)(r * 128 + (((ch ^ (r & 7)) & 7) << 4));
                ldsm4(bF[0][p], stb + B128_OFF + o);
            }
        }
#pragma unroll
        for (int ks = 0; ks < 4; ks++) {
            const int cur = ks & 1, nxt = cur ^ 1;
            if (ks < 3) {
                const int kc = (ks + 1) * 2;
#pragma unroll
                for (int mf = 0; mf < 4; mf++) {
                    int r = wm0 + mf * 16 + aRow;
                    int ch = kc + aSel;
                    uint32_t o = (uint32_t)(r * 128 + (((ch ^ (r & 7)) & 7) << 4));
                    ldsm4(aF[nxt][mf], stb + A128_OFF + o);
                }
#pragma unroll
                for (int p = 0; p < 2; p++) {
                    int r = wn0 + p * 16 + bRow;
                    int ch = kc + bSel;
                    uint32_t o = (uint32_t)(r * 128 + (((ch ^ (r & 7)) & 7) << 4));
                    ldsm4(bF[nxt][p], stb + B128_OFF + o);
                }
            }
#pragma unroll
            for (int mf = 0; mf < 4; mf++) {
#pragma unroll
                for (int nf = 0; nf < 4; nf++) {
                    mma16816(acc[mf][nf], aF[cur][mf], &bF[cur][nf >> 1][(nf & 1) * 2]);
                }
            }
        }
    }
}

// ---------------- fused big kernel: mention scores + C1 (fp16) ----------------
__global__ __launch_bounds__(256, 1)
void gemm_big(const __half* __restrict__ eF,
              const __half* __restrict__ wmF, const __half* __restrict__ wcF,
              const float* __restrict__ wo, float* __restrict__ rowAcc,
              __half* __restrict__ C1)
{
    extern __shared__ char smem[];
    const bool isMen = blockIdx.x < 4;
    const int n0 = (blockIdx.x & 3) * 256;
    const int m0 = blockIdx.y * 128;
    const int lane = threadIdx.x & 31;
    const int wid  = threadIdx.x >> 5;
    const int wm0  = (wid >> 2) * 64;
    const int wn0  = (wid & 3) * 64;

    float acc[4][8][4];
    gemm_core(eF, DIM, isMen ? wmF : wcF, DIM, DIM, DIM, m0, n0, smem, acc);

    const int g = lane >> 2, t = lane & 3;
    if (isMen) {
#pragma unroll
        for (int mf = 0; mf < 4; mf++) {
            float s0 = 0.0f, s1 = 0.0f;
#pragma unroll
            for (int nf = 0; nf < 8; nf++) {
#pragma unroll
                for (int q = 0; q < 2; q++) {
                    int n = n0 + wn0 + nf * 8 + 2 * t + q;
                    float w = wo[n];
                    s0 += ftanh(acc[mf][nf][q])     * w;
                    s1 += ftanh(acc[mf][nf][2 + q]) * w;
                }
            }
            s0 += __shfl_xor_sync(0xffffffffu, s0, 1);
            s0 += __shfl_xor_sync(0xffffffffu, s0, 2);
            s1 += __shfl_xor_sync(0xffffffffu, s1, 1);
            s1 += __shfl_xor_sync(0xffffffffu, s1, 2);
            if (t == 0) {
                int m = m0 + wm0 + mf * 16 + g;
                atomicAdd(&rowAcc[m], s0);
                atomicAdd(&rowAcc[m + 8], s1);
            }
        }
    } else {
#pragma unroll
        for (int mf = 0; mf < 4; mf++) {
            int mA = m0 + wm0 + mf * 16 + g;
#pragma unroll
            for (int nf = 0; nf < 8; nf++) {
                int n = n0 + wn0 + nf * 8 + 2 * t;
                size_t iA = (size_t)mA * DIM + n;
                size_t iB = (size_t)(mA + 8) * DIM + n;
                *reinterpret_cast<__half2*>(C1 + iA) =
                    __floats2half2_rn(acc[mf][nf][0], acc[mf][nf][1]);
                *reinterpret_cast<__half2*>(C1 + iB) =
                    __floats2half2_rn(acc[mf][nf][2], acc[mf][nf][3]);
            }
        }
    }
}

// ---------------- generic GEMM kernel (STORE epilogue) -------------------------
__global__ __launch_bounds__(256, 1)
void gemm_hf_store(const __half* __restrict__ A_, int lda,
                   const __half* __restrict__ B_, int ldb,
                   float* __restrict__ C, int ldc, int N, int K)
{
    extern __shared__ char smem[];
    const int n0 = blockIdx.x * 256;
    const int m0 = blockIdx.y * 128;
    const int lane = threadIdx.x & 31;
    const int wid  = threadIdx.x >> 5;
    const int wm0  = (wid >> 2) * 64;
    const int wn0  = (wid & 3) * 64;

    float acc[4][8][4];
    gemm_core(A_, lda, B_, ldb, N, K, m0, n0, smem, acc);

    const int g = lane >> 2, t = lane & 3;
#pragma unroll
    for (int mf = 0; mf < 4; mf++) {
        int mA = m0 + wm0 + mf * 16 + g;
#pragma unroll
        for (int nf = 0; nf < 8; nf++) {
            int n = n0 + wn0 + nf * 8 + 2 * t;
#pragma unroll
            for (int q = 0; q < 2; q++) {
                int nn = n + q;
                if (nn < N) {
                    C[(size_t)mA * ldc + nn]       = acc[mf][nf][q];
                    C[(size_t)(mA + 8) * ldc + nn] = acc[mf][nf][2 + q];
                }
            }
        }
    }
}

// ---------------- split-K GEMM, 128-wide tile, atomicAdd (latent) --------------
__global__ __launch_bounds__(256, 1)
void gemm_ks128(const __half* __restrict__ A_, int lda,
                const __half* __restrict__ B_, int ldb,
                float* __restrict__ C, int ldc, int N, int Kslice)
{
    extern __shared__ char smem[];
    const int n0 = blockIdx.x * 128;
    const int m0 = blockIdx.y * 128;
    const int kofs = blockIdx.z * Kslice;
    const int lane = threadIdx.x & 31;
    const int wid  = threadIdx.x >> 5;
    const int wm0  = (wid >> 2) * 64;
    const int wn0  = (wid & 3) * 32;

    float acc[4][4][4];
    gemm_core128(A_ + kofs, lda, B_ + kofs, ldb, N, Kslice, m0, n0, smem, acc);

    const int g = lane >> 2, t = lane & 3;
#pragma unroll
    for (int mf = 0; mf < 4; mf++) {
        int mA = m0 + wm0 + mf * 16 + g;
#pragma unroll
        for (int nf = 0; nf < 4; nf++) {
            int n = n0 + wn0 + nf * 8 + 2 * t;
#pragma unroll
            for (int q = 0; q < 2; q++) {
                int nn = n + q;
                if (nn < N) {
                    atomicAdd(&C[(size_t)mA * ldc + nn],       acc[mf][nf][q]);
                    atomicAdd(&C[(size_t)(mA + 8) * ldc + nn], acc[mf][nf][2 + q]);
                }
            }
        }
    }
}

// ---------------- fused output head: out_lat + out_main (tile 128x128) --------
__global__ __launch_bounds__(256, 1)
void gemm_outfused(const __half* __restrict__ latF,
                   const __half* __restrict__ l2lF,
                   const __half* __restrict__ fF,
                   const __half* __restrict__ woF,
                   float* __restrict__ outLat,
                   float* __restrict__ outMain,
                   const float* __restrict__ scal)
{
    extern __shared__ char smem[];
    const int n0 = blockIdx.x * 128;
    const int m0 = blockIdx.y * 128;
    const int lane = threadIdx.x & 31;
    const int wid  = threadIdx.x >> 5;
    const int wm0  = (wid >> 2) * 64;
    const int wn0  = (wid & 3) * 32;

    float accL[4][4][4];
    gemm_core128(latF, LATP, l2lF, LATP, LBL, LATP, m0, n0, smem, accL);
    __syncthreads();

    float acc[4][4][4];
    gemm_core128(fF, DIM2, woF, DIM2, LBL, DIM2, m0, n0, smem, acc);

    const int g = lane >> 2, t = lane & 3;
    const float ls = *scal;
#pragma unroll
    for (int mf = 0; mf < 4; mf++) {
        int mA = m0 + wm0 + mf * 16 + g;
#pragma unroll
        for (int nf = 0; nf < 4; nf++) {
            int n = n0 + wn0 + nf * 8 + 2 * t;
#pragma unroll
            for (int q = 0; q < 2; q++) {
                int nn = n + q;
                if (nn < LBL) {
                    size_t iA = (size_t)mA * LBL + nn;
                    size_t iB = (size_t)(mA + 8) * LBL + nn;
                    float l0 = accL[mf][nf][q];
                    float l1 = accL[mf][nf][2 + q];
                    outLat[iA]  = l0;
                    outLat[iB]  = l1;
                    outMain[iA] = acc[mf][nf][q]     + ls * l0;
                    outMain[iB] = acc[mf][nf][2 + q] + ls * l1;
                }
            }
        }
    }
}

// ---------------- mention: masked softmax + weighted sum (fp16) ---------------
__global__ void attn_kernel(const __half* __restrict__ elmoF,
                            const int* __restrict__ gathers,
                            const float* __restrict__ scores,
                            const float* __restrict__ mask,
                            __half* __restrict__ outF)
{
    int b = blockIdx.x;
    int tid = threadIdx.x;
    __shared__ float attn_s[SEQ];
    __shared__ float red[8];
    int g = gathers[b];

    float sc = -1e30f;
    if (tid < SEQ) {
        float raw = scores[g * SEQ + tid];
        sc = raw + (1.0f - mask[b * SEQ + tid]) * NEGV;
    }
    float v = sc;
#pragma unroll
    for (int off = 16; off > 0; off >>= 1)
        v = fmaxf(v, __shfl_xor_sync(0xffffffffu, v, off));
    if ((tid & 31) == 0) red[tid >> 5] = v;
    __syncthreads();
    float mx = fmaxf(fmaxf(red[0], red[1]), fmaxf(red[2], red[3]));
    __syncthreads();

    float e = (tid < SEQ) ? __expf(sc - mx) : 0.0f;
    v = e;
#pragma unroll
    for (int off = 16; off > 0; off >>= 1)
        v += __shfl_xor_sync(0xffffffffu, v, off);
    if ((tid & 31) == 0) red[tid >> 5] = v;
    __syncthreads();
    float sum = red[0] + red[1] + red[2] + red[3];
    if (tid < SEQ) attn_s[tid] = e / sum;
    __syncthreads();

    const uint2* xr = reinterpret_cast<const uint2*>(elmoF + (size_t)g * SEQ * DIM);
    float4 accv = make_float4(0.f, 0.f, 0.f, 0.f);
#pragma unroll 4
    for (int s = 0; s < SEQ; s++) {
        float a = attn_s[s];
        uint2 xp = xr[(size_t)s * (DIM / 4) + tid];
        float2 x0 = __half22float2(*reinterpret_cast<__half2*>(&xp.x));
        float2 x1 = __half22float2(*reinterpret_cast<__half2*>(&xp.y));
        accv.x = fmaf(a, x0.x, accv.x);
        accv.y = fmaf(a, x0.y, accv.y);
        accv.z = fmaf(a, x1.x, accv.z);
        accv.w = fmaf(a, x1.y, accv.w);
    }
    size_t idx = (size_t)b * DIM2 + 4 * tid;
    __half2 h0 = __floats2half2_rn(accv.x, accv.y);
    __half2 h1 = __floats2half2_rn(accv.z, accv.w);
    uint2 o;
    o.x = *reinterpret_cast<uint32_t*>(&h0);
    o.y = *reinterpret_cast<uint32_t*>(&h1);
    *reinterpret_cast<uint2*>(outF + idx) = o;
}

// ---------------- fused context: score + softmax + weighted sum ----------------
__global__ void ctx_fused_kernel(const int* __restrict__ gathers,
                                 const float* __restrict__ dist,
                                 const float* __restrict__ wd,
                                 const float* __restrict__ wo,
                                 const float* __restrict__ mask,
                                 const __half* __restrict__ elmoF,
                                 __half* __restrict__ outF)
{
    int b = blockIdx.x;
    int tid = threadIdx.x;
    int w = tid >> 5, lid = tid & 31;
    __shared__ __align__(16) float s_m2[DIM];
    __shared__ __align__(16) float s_wd[DIM];
    __shared__ __align__(16) float s_wo[DIM];
    __shared__ float s_score[SEQ];
    __shared__ float attn_s[SEQ];
    __shared__ float red[8];
    int g = gathers[b];
    for (int i = tid; i < DIM; i += 256) {
        s_m2[i] = g_m2[(size_t)b * DIM + i];
        s_wd[i] = wd[i];
        s_wo[i] = wo[i];
    }
    __syncthreads();

    const uint2* c1 = reinterpret_cast<const uint2*>(g_C1h + (size_t)g * SEQ * DIM);
    const float4* m2v = reinterpret_cast<const float4*>(s_m2);
    const float4* wdv = reinterpret_cast<const float4*>(s_wd);
    const float4* wov = reinterpret_cast<const float4*>(s_wo);

    for (int s = w; s < SEQ; s += 8) {
        float dv = dist[b * SEQ + s];
        float p = 0.0f;
#pragma unroll
        for (int j0 = 0; j0 < 8; j0++) {
            int j = lid + j0 * 32;
            uint2 cp = c1[(size_t)s * (DIM / 4) + j];
            float2 c0 = __half22float2(*reinterpret_cast<__half2*>(&cp.x));
            float2 c1f = __half22float2(*reinterpret_cast<__half2*>(&cp.y));
            float4 m = m2v[j], d = wdv[j], o = wov[j];
            p += o.x * ftanh(c0.x  + m.x + dv * d.x)
               + o.y * ftanh(c0.y  + m.y + dv * d.y)
               + o.z * ftanh(c1f.x + m.z + dv * d.z)
               + o.w * ftanh(c1f.y + m.w + dv * d.w);
        }
#pragma unroll
        for (int off = 16; off > 0; off >>= 1)
            p += __shfl_xor_sync(0xffffffffu, p, off);
        if (lid == 0) s_score[s] = p;
    }
    __syncthreads();

    float sc = -1e30f;
    if (tid < SEQ)
        sc = s_score[tid] + (1.0f - mask[b * SEQ + tid]) * NEGV;
    float v = sc;
#pragma unroll
    for (int off = 16; off > 0; off >>= 1)
        v = fmaxf(v, __shfl_xor_sync(0xffffffffu, v, off));
    if ((tid & 31) == 0) red[tid >> 5] = v;
    __syncthreads();
    float mx = fmaxf(fmaxf(red[0], red[1]), fmaxf(red[2], red[3]));
    __syncthreads();
    float e = (tid < SEQ) ? __expf(sc - mx) : 0.0f;
    v = e;
#pragma unroll
    for (int off = 16; off > 0; off >>= 1)
        v += __shfl_xor_sync(0xffffffffu, v, off);
    if ((tid & 31) == 0) red[tid >> 5] = v;
    __syncthreads();
    float sum = red[0] + red[1] + red[2] + red[3];
    if (tid < SEQ) attn_s[tid] = e / sum;
    __syncthreads();

    const uint2* xr = reinterpret_cast<const uint2*>(elmoF + (size_t)g * SEQ * DIM);
    float4 accv = make_float4(0.f, 0.f, 0.f, 0.f);
#pragma unroll 4
    for (int s = 0; s < SEQ; s++) {
        float a = attn_s[s];
        uint2 xp = xr[(size_t)s * (DIM / 4) + tid];
        float2 x0 = __half22float2(*reinterpret_cast<__half2*>(&xp.x));
        float2 x1 = __half22float2(*reinterpret_cast<__half2*>(&xp.y));
        accv.x = fmaf(a, x0.x, accv.x);
        accv.y = fmaf(a, x0.y, accv.y);
        accv.z = fmaf(a, x1.x, accv.z);
        accv.w = fmaf(a, x1.y, accv.w);
    }
    size_t idx = (size_t)b * DIM2 + DIM + 4 * tid;
    __half2 h0 = __floats2half2_rn(accv.x, accv.y);
    __half2 h1 = __floats2half2_rn(accv.z, accv.w);
    uint2 o;
    o.x = *reinterpret_cast<uint32_t*>(&h0);
    o.y = *reinterpret_cast<uint32_t*>(&h1);
    *reinterpret_cast<uint2*>(outF + idx) = o;
}

// ---------------- launch ------------------------------------------------------
extern "C" void kernel_launch(void* const* d_in, const int* in_sizes, int n_in,
                              void* d_out, int out_size)
{
    const float* elmo     = (const float*)d_in[0];
    const float* men_mask = (const float*)d_in[1];
    const float* ctx_mask = (const float*)d_in[2];
    const float* dist     = (const float*)d_in[3];
    const int*   gathers  = (const int*)  d_in[4];
    const float* W_men_m  = (const float*)d_in[5];
    const float* W_men_o  = (const float*)d_in[6];
    const float* W_ctx_c  = (const float*)d_in[7];
    const float* W_ctx_m  = (const float*)d_in[8];
    const float* w_ctx_d  = (const float*)d_in[9];
    const float* W_ctx_o  = (const float*)d_in[10];
    const float* W_out    = (const float*)d_in[11];
    const float* W_f2l    = (const float*)d_in[12];
    const float* W_l2l    = (const float*)d_in[13];
    const float* lscal    = (const float*)d_in[14];

    float* out_main = (float*)d_out;
    float* out_lat  = out_main + (size_t)BATCH * LBL;

    float *pMS, *pM2, *pLat32;
    __half* pC1;
    cudaGetSymbolAddress((void**)&pC1,    g_C1h);
    cudaGetSymbolAddress((void**)&pMS,    g_menScore);
    cudaGetSymbolAddress((void**)&pM2,    g_m2);
    cudaGetSymbolAddress((void**)&pLat32, g_lat32);
    __half *pEF, *pWmF, *pWcF, *pWcmF, *pWoF, *pl2lF, *pf2lF, *pFF, *pLaF;
    cudaGetSymbolAddress((void**)&pEF,   g_eF);
    cudaGetSymbolAddress((void**)&pWmF,  g_WmF);
    cudaGetSymbolAddress((void**)&pWcF,  g_WcF);
    cudaGetSymbolAddress((void**)&pWcmF, g_WcmF);
    cudaGetSymbolAddress((void**)&pWoF,  g_WoF);
    cudaGetSymbolAddress((void**)&pl2lF, g_Wl2lF);
    cudaGetSymbolAddress((void**)&pf2lF, g_Wf2lF);
    cudaGetSymbolAddress((void**)&pFF,   g_fF);
    cudaGetSymbolAddress((void**)&pLaF,  g_latF);

    cudaFuncSetAttribute(gemm_big,      cudaFuncAttributeMaxDynamicSharedMemorySize, SMEM_GEMM);
    cudaFuncSetAttribute(gemm_hf_store, cudaFuncAttributeMaxDynamicSharedMemorySize, SMEM_GEMM);
    cudaFuncSetAttribute(gemm_ks128,    cudaFuncAttributeMaxDynamicSharedMemorySize, SMEM_GEMM128);
    cudaFuncSetAttribute(gemm_outfused, cudaFuncAttributeMaxDynamicSharedMemorySize, SMEM_GEMM128);

    const int nDD4 = (DIM * DIM) / 4;

    // 0. elmo fp32->fp16
    {
        int n4 = (N_SENTC * SEQ * DIM) / 4;
        cvt_f16<<<(n4 + 255) / 256, 256>>>(elmo, pEF, n4);
    }
    // 1. W_men_m + W_ctx_c in one launch
    cvt2_f16<<<(2 * nDD4 + 255) / 256, 256>>>(W_men_m, pWmF, W_ctx_c, pWcF, nDD4);
    // 2. zero menScore + lat32
    {
        int ntot = N_SENTC * SEQ + BATCH * LATP;
        zero2_kernel<<<(ntot + 255) / 256, 256>>>(pMS, N_SENTC * SEQ, pLat32, BATCH * LATP);
    }

    // 3. fused big GEMM (ncu window: launch index 3)
    gemm_big<<<dim3(8, 256), 256, SMEM_GEMM>>>(pEF, pWmF, pWcF, W_men_o, pMS, pC1);

    // 4-7. remaining conversions
    cvt_f16<<<(nDD4 + 255) / 256, 256>>>(W_ctx_m, pWcmF, nDD4);
    {
        int n4o = (int)(((size_t)LBL * DIM2) / 4);
        cvt_f16<<<(n4o + 255) / 256, 256>>>(W_out, pWoF, n4o);
    }
    cvt_l2l<<<(LBL * LATP + 255) / 256, 256>>>(W_l2l, pl2lF);
    {
        int n4f = (LATD * DIM2) / 4;
        cvt_f16<<<(n4f + 255) / 256, 256>>>(W_f2l, pf2lF, n4f);
    }

    // 8. mention softmax + men_repr -> fF cols [0,1024)
    attn_kernel<<<BATCH, 256>>>(pEF, gathers, pMS, men_mask, pFF);

    // 9. m2 = men_repr @ W_ctx_m^T (R14 form)
    gemm_hf_store<<<dim3(4, 4), 256, SMEM_GEMM>>>(
        pFF, DIM2, pWcmF, DIM, pM2, DIM, DIM, DIM);

    // 10. fused context: score + softmax + ctx_repr -> fF cols [1024,2048)
    ctx_fused_kernel<<<BATCH, 256>>>(gathers, dist, w_ctx_d, W_ctx_o,
                                     ctx_mask, pEF, pFF);

    // 11. latent = final @ W_f2l^T, split-K 8x256 -> atomicAdd (32 CTAs)
    gemm_ks128<<<dim3(1, 4, 8), 256, SMEM_GEMM128>>>(
        pFF, DIM2, pf2lF, DIM2, pLat32, LATP, LATD, 256);

    // 12. pack latent fp32 -> fp16
    cvt_lat<<<(BATCH * LATP + 255) / 256, 256>>>(pLat32, pLaF);

    // 13. fused output head: out_lat + out_main in one pass (tile 128x128)
    gemm_outfused<<<dim3((LBL + 127) / 128, 4), 256, SMEM_GEMM128>>>(
        pLaF, pl2lF, pFF, pWoF, out_lat, out_main, lscal);
}